// round 15
// baseline (speedup 1.0000x reference)
#include <cuda_runtime.h>

typedef unsigned long long ULL;

#define NBLK   128
#define NTHR   512
#define ROWS   32      // batch rows per block
#define T128   128
#define STEPS  60
#define HPU    34      // ULL stride per k-row of duplicated h (even -> 16B aligned)

__device__ __forceinline__ ULL fma2(ULL a, ULL b, ULL c) {
    ULL d;
    asm("fma.rn.f32x2 %0, %1, %2, %3;" : "=l"(d) : "l"(a), "l"(b), "l"(c));
    return d;
}
__device__ __forceinline__ ULL pack2(float x, float y) {
    ULL r;
    asm("mov.b64 %0, {%1, %2};" : "=l"(r) : "f"(x), "f"(y));
    return r;
}
__device__ __forceinline__ void unpack2(ULL v, float& x, float& y) {
    asm("mov.b64 {%0, %1}, %2;" : "=f"(x), "=f"(y) : "l"(v));
}
__device__ __forceinline__ float ex2f_(float x) {
    float y; asm("ex2.approx.f32 %0, %1;" : "=f"(y) : "f"(x)); return y;
}
__device__ __forceinline__ float rcpf_(float x) {
    float y; asm("rcp.approx.f32 %0, %1;" : "=f"(y) : "f"(x)); return y;
}
__device__ __forceinline__ float sigm(float x) {
    return rcpf_(1.0f + ex2f_(-1.4426950408889634f * x));
}
__device__ __forceinline__ float tanh_(float x) {
    return fmaf(2.0f, rcpf_(1.0f + ex2f_(-2.8853900817779268f * x)), -1.0f);
}

// 8 k-iters, single matvec, dup-h: acc += W[k][j][.] * hdup[k][R0 + r]  (NO ALU movs)
__device__ __forceinline__ void mv8d(const float* __restrict__ Wb,
                                     const ULL* __restrict__ hd,
                                     int j, int R0, int kb,
                                     ULL aif[4], ULL ago[4]) {
#pragma unroll 4
    for (int kk = 0; kk < 8; kk++) {
        int k = kb * 8 + kk;
        ulonglong2 w = *(const ulonglong2*)(Wb + ((k * 64 + j) << 2)); // (i,f),(g,o)
        const ULL* hr = hd + k * HPU + R0;
        ulonglong2 hA = *(const ulonglong2*)(hr);       // rows R0, R0+1 (dup)
        ulonglong2 hB = *(const ulonglong2*)(hr + 2);   // rows R0+2, R0+3
        aif[0] = fma2(w.x, hA.x, aif[0]); ago[0] = fma2(w.y, hA.x, ago[0]);
        aif[1] = fma2(w.x, hA.y, aif[1]); ago[1] = fma2(w.y, hA.y, ago[1]);
        aif[2] = fma2(w.x, hB.x, aif[2]); ago[2] = fma2(w.y, hB.x, ago[2]);
        aif[3] = fma2(w.x, hB.y, aif[3]); ago[3] = fma2(w.y, hB.y, ago[3]);
    }
}

// 8 k-iters, fused: one dup-h load feeds BOTH (Wih1 -> a1) and (Whh0 -> a0next)
__device__ __forceinline__ void mv8d_fused(const float* __restrict__ W1b,
                                           const float* __restrict__ W0b,
                                           const ULL* __restrict__ hd,
                                           int j, int R0, int kb,
                                           ULL aif1[4], ULL ago1[4],
                                           ULL aif0[4], ULL ago0[4]) {
#pragma unroll 2
    for (int kk = 0; kk < 8; kk++) {
        int k = kb * 8 + kk;
        ulonglong2 w1 = *(const ulonglong2*)(W1b + ((k * 64 + j) << 2));
        ulonglong2 w0 = *(const ulonglong2*)(W0b + ((k * 64 + j) << 2));
        const ULL* hr = hd + k * HPU + R0;
        ulonglong2 hA = *(const ulonglong2*)(hr);
        ulonglong2 hB = *(const ulonglong2*)(hr + 2);
        aif1[0] = fma2(w1.x, hA.x, aif1[0]); ago1[0] = fma2(w1.y, hA.x, ago1[0]);
        aif0[0] = fma2(w0.x, hA.x, aif0[0]); ago0[0] = fma2(w0.y, hA.x, ago0[0]);
        aif1[1] = fma2(w1.x, hA.y, aif1[1]); ago1[1] = fma2(w1.y, hA.y, ago1[1]);
        aif0[1] = fma2(w0.x, hA.y, aif0[1]); ago0[1] = fma2(w0.y, hA.y, ago0[1]);
        aif1[2] = fma2(w1.x, hB.x, aif1[2]); ago1[2] = fma2(w1.y, hB.x, ago1[2]);
        aif0[2] = fma2(w0.x, hB.x, aif0[2]); ago0[2] = fma2(w0.y, hB.x, ago0[2]);
        aif1[3] = fma2(w1.x, hB.y, aif1[3]); ago1[3] = fma2(w1.y, hB.y, ago1[3]);
        aif0[3] = fma2(w0.x, hB.y, aif0[3]); ago0[3] = fma2(w0.y, hB.y, ago0[3]);
    }
}

// one row of LSTM pointwise -> new c (in-place), returns new h
__device__ __forceinline__ float cell_row(ULL aif, ULL ago, float& c) {
    float gi, gf, gg, go;
    unpack2(aif, gi, gf);
    unpack2(ago, gg, go);
    float cn = sigm(gf) * c + sigm(gi) * tanh_(gg);
    c = cn;
    return sigm(go) * tanh_(cn);
}

// SMEM layout (floats): W repack W[(k*64+j)*4+g] = Wsrc[(g*64+j)*64+k]
#define OFF_W0    0                       // Whh0  [64][64][4]
#define OFF_W1IH  (OFF_W0 + 16384)        // Wih1
#define OFF_W1HH  (OFF_W1IH + 16384)      // Whh1
#define OFF_H0D   (OFF_W1HH + 16384)      // hdup0 [64][HPU] ULL
#define OFF_H1D   (OFF_H0D + 64 * HPU * 2)
#define OFF_XS    (OFF_H1D + 64 * HPU * 2)  // xs[32][4]
#define SMEM_FLOATS (OFF_XS + ROWS * 4)   // 57984 floats = 231936 B

__global__ __launch_bounds__(NTHR, 1)
void lstm_persist_kernel(const float* __restrict__ x,
                         const float* __restrict__ Wih0, const float* __restrict__ Whh0,
                         const float* __restrict__ bih0, const float* __restrict__ bhh0,
                         const float* __restrict__ Wih1, const float* __restrict__ Whh1,
                         const float* __restrict__ bih1, const float* __restrict__ bhh1,
                         const float* __restrict__ Wfc,  const float* __restrict__ bfc,
                         float* __restrict__ out) {
    extern __shared__ float sm[];
    float* W0h  = sm + OFF_W0;
    float* W1i  = sm + OFF_W1IH;
    float* W1h  = sm + OFF_W1HH;
    ULL* hdup0  = (ULL*)(sm + OFF_H0D);
    ULL* hdup1  = (ULL*)(sm + OFF_H1D);
    float* xs   = sm + OFF_XS;

    const int t = threadIdx.x;
    const int rowbase = blockIdx.x * ROWS;

    // ---- one-time staging ----
    for (int idx = t; idx < 16384; idx += NTHR) {
        int g = idx & 3, jj = (idx >> 2) & 63, k = idx >> 8;
        W0h[idx] = Whh0[(g * 64 + jj) * 64 + k];
        W1i[idx] = Wih1[(g * 64 + jj) * 64 + k];
        W1h[idx] = Whh1[(g * 64 + jj) * 64 + k];
    }
    for (int idx = t; idx < 64 * HPU; idx += NTHR) { hdup0[idx] = 0ULL; hdup1[idx] = 0ULL; }
    if (t < ROWS * 4)
        xs[t] = x[((size_t)(rowbase + (t >> 2)) * T128) * 4 + (t & 3)];

    // ---- warp tiling: 16 j x 2 row-groups per warp ----
    const int wid = t >> 5, l = t & 31;
    const int j  = (wid & 3) * 16 + (l & 15);
    const int R0 = (wid >> 2) * 8 + (l >> 4) * 4;

    const ULL bif0 = pack2(bih0[j] + bhh0[j],             bih0[64 + j] + bhh0[64 + j]);
    const ULL bgo0 = pack2(bih0[128 + j] + bhh0[128 + j], bih0[192 + j] + bhh0[192 + j]);
    const ULL bif1 = pack2(bih1[j] + bhh1[j],             bih1[64 + j] + bhh1[64 + j]);
    const ULL bgo1 = pack2(bih1[128 + j] + bhh1[128 + j], bih1[192 + j] + bhh1[192 + j]);
    ULL wif0x[4], wgo0x[4];
#pragma unroll
    for (int d = 0; d < 4; d++) {
        wif0x[d] = pack2(Wih0[j * 4 + d],         Wih0[(64 + j) * 4 + d]);
        wgo0x[d] = pack2(Wih0[(128 + j) * 4 + d], Wih0[(192 + j) * 4 + d]);
    }
    const float bfr = (t < 128) ? bfc[t & 3] : 0.0f;

    float c0[4], c1[4];
    ULL aif0[4], ago0[4], aif1[4], ago1[4];
#pragma unroll
    for (int r = 0; r < 4; r++) {
        c0[r] = 0.0f; c1[r] = 0.0f;
        aif0[r] = bif0; ago0[r] = bgo0;   // carried a0 for step 0 (h0_prev = 0)
    }
    __syncthreads();

    ULL* const h0dst = hdup0 + j * HPU + R0;
    ULL* const h1dst = hdup1 + j * HPU + R0;

    for (int s = 0; s < T128 + STEPS; s++) {
        // ---- x-part of layer-0 gates (a0 carries b0 + Whh0*h0_prev from fused loop) ----
#pragma unroll
        for (int r = 0; r < 4; r++) {
            float4 xv = *(const float4*)(xs + (R0 + r) * 4);
            ULL x0 = pack2(xv.x, xv.x), x1 = pack2(xv.y, xv.y);
            ULL x2 = pack2(xv.z, xv.z), x3 = pack2(xv.w, xv.w);
            aif0[r] = fma2(wif0x[0], x0, aif0[r]); ago0[r] = fma2(wgo0x[0], x0, ago0[r]);
            aif0[r] = fma2(wif0x[1], x1, aif0[r]); ago0[r] = fma2(wgo0x[1], x1, ago0[r]);
            aif0[r] = fma2(wif0x[2], x2, aif0[r]); ago0[r] = fma2(wgo0x[2], x2, ago0[r]);
            aif0[r] = fma2(wif0x[3], x3, aif0[r]); ago0[r] = fma2(wgo0x[3], x3, ago0[r]);
        }

        // ---- phase 1: a1 = b1 + Whh1*h1_old, interleaved cell0 + immediate dup store
        // (safe: old hdup0's readers finished before B2 of previous step)
#pragma unroll
        for (int r = 0; r < 4; r++) { aif1[r] = bif1; ago1[r] = bgo1; }
#pragma unroll 1
        for (int kb = 0; kb < 8; kb++) {
            mv8d(W1h, hdup1, j, R0, kb, aif1, ago1);
            if (kb & 1) {
                int r = kb >> 1;
                float h = cell_row(aif0[r], ago0[r], c0[r]);   // MUFU hides under FMA
                h0dst[r] = pack2(h, h);
            }
        }
        __syncthreads();                                      // B1: new h0 visible

        // prefetch next x (encode phase) — latency hides under fused loop
        float xpre = 0.0f;
        const bool ldx = (s + 1 < T128) && (t < ROWS * 4);
        if (ldx)
            xpre = x[((size_t)(rowbase + (t >> 2)) * T128 + (s + 1)) * 4 + (t & 3)];

        // ---- fused phase: a1 += Wih1*h0_new ; a0_next = b0 + Whh0*h0_new ----
#pragma unroll
        for (int r = 0; r < 4; r++) { aif0[r] = bif0; ago0[r] = bgo0; }
#pragma unroll 1
        for (int kb = 0; kb < 8; kb++)
            mv8d_fused(W1i, W0h, hdup0, j, R0, kb, aif1, ago1, aif0, ago0);

        // ---- cell1 burst -> dup h1 store ----
        {
            float ha = cell_row(aif1[0], ago1[0], c1[0]);
            float hb = cell_row(aif1[1], ago1[1], c1[1]);
            float hc = cell_row(aif1[2], ago1[2], c1[2]);
            float hd = cell_row(aif1[3], ago1[3], c1[3]);
            ulonglong2 v0, v1;
            v0.x = pack2(ha, ha); v0.y = pack2(hb, hb);
            v1.x = pack2(hc, hc); v1.y = pack2(hd, hd);
            *(ulonglong2*)h1dst = v0;
            *(ulonglong2*)(h1dst + 2) = v1;
        }
        __syncthreads();                                      // B2: new h1 visible

        // ---- head (AR) / next-step input staging ----
        if (t < ROWS * 4) {
            int r = t >> 2, d = t & 3;
            if (s >= T128) {
                const float* h1f = (const float*)hdup1;
                float p = bfr;
#pragma unroll 4
                for (int k = 0; k < 64; k++)
                    p = fmaf(__ldg(Wfc + d * 64 + k), h1f[(k * HPU + r) * 2], p);
                xs[t] = p;
                out[((size_t)(rowbase + r) * STEPS + (s - T128)) * 4 + d] = p;
            } else if (ldx) {
                xs[t] = xpre;  // encode phase (s==127 keeps x[127] for s==128)
            }
        }
        __syncthreads();                                      // B3: xs visible
    }
}

extern "C" void kernel_launch(void* const* d_in, const int* in_sizes, int n_in,
                              void* d_out, int out_size) {
    const float* x    = (const float*)d_in[0];
    const float* Wih0 = (const float*)d_in[1];
    const float* Whh0 = (const float*)d_in[2];
    const float* bih0 = (const float*)d_in[3];
    const float* bhh0 = (const float*)d_in[4];
    const float* Wih1 = (const float*)d_in[5];
    const float* Whh1 = (const float*)d_in[6];
    const float* bih1 = (const float*)d_in[7];
    const float* bhh1 = (const float*)d_in[8];
    const float* Wfc  = (const float*)d_in[9];
    const float* bfc  = (const float*)d_in[10];

    const int smem_bytes = SMEM_FLOATS * (int)sizeof(float);  // 231936 B
    cudaFuncSetAttribute(lstm_persist_kernel,
                         cudaFuncAttributeMaxDynamicSharedMemorySize, smem_bytes);
    lstm_persist_kernel<<<NBLK, NTHR, smem_bytes>>>(
        x, Wih0, Whh0, bih0, bhh0, Wih1, Whh1, bih1, bhh1, Wfc, bfc, (float*)d_out);
}